// round 10
// baseline (speedup 1.0000x reference)
#include <cuda_runtime.h>
#include <cuda_fp16.h>
#include <math.h>
#include <cstdint>

#define NN 16384
#define DD 512
#define OO 512
#define BM 64
#define BN 64
#define BK 64                   // k-tile in elements (fp16)
#define NKT (DD / BK)           // 8 k-tiles
#define LH 72                   // smem fp16 per row (144B) -> conflict-free ldmatrix
#define TXH (BM * LH)           // 4608 halfs, X tile
#define TBH (BN * LH)           // 4608 halfs, P or A tile
#define STAGE_H (TXH + 2 * TBH) // 13824 halfs = 27648 B
#define NSTG 4
#define SMEM_BYTES (NSTG * STAGE_H * 2)  // 110592 B -> 2 CTAs/SM
#define MINN 1e-15f

// Precomputed stats + fp16 operand copies (no allocations -> device globals).
__device__ float g_a0[NN];    // 1 + ||x||^2
__device__ float g_rr[NN];    // 2 / (1 - ||x||^2)
__device__ float g_B[OO];     // 1 - ||p||^2   (fp64-accurate)
__device__ float g_pa[OO];    // <p, a>
__device__ float g_q[OO];     // 1 / (B * ||a||)
__device__ float g_e2[OO];    // ln(2) * exp(scale)
__device__ __half g_Xh[NN * DD];
__device__ __half g_Ph[OO * DD];
__device__ __half g_Ah[OO * DD];

__device__ __forceinline__ float warp_sum(float v) {
#pragma unroll
    for (int s = 16; s > 0; s >>= 1) v += __shfl_xor_sync(0xffffffffu, v, s);
    return v;
}
__device__ __forceinline__ double warp_sum_d(double v) {
#pragma unroll
    for (int s = 16; s > 0; s >>= 1) v += __shfl_xor_sync(0xffffffffu, v, s);
    return v;
}
__device__ __forceinline__ uint2 cvt4(float4 v) {
    __half2 h0 = __floats2half2_rn(v.x, v.y);
    __half2 h1 = __floats2half2_rn(v.z, v.w);
    uint2 u;
    u.x = *reinterpret_cast<uint32_t*>(&h0);
    u.y = *reinterpret_cast<uint32_t*>(&h1);
    return u;
}

// ---------------- fused prep: X convert + x-stats | P/A convert + o-stats ----
__global__ void prep(const float* __restrict__ X, const float* __restrict__ P,
                     const float* __restrict__ A, const float* __restrict__ S) {
    int bid = blockIdx.x;
    int tid = threadIdx.x;
    int wid = tid >> 5, lane = tid & 31;
    if (bid < 2048) {
        int row = bid * 8 + wid;
        const float4* x4 = reinterpret_cast<const float4*>(X + (size_t)row * DD);
        uint2* xh = reinterpret_cast<uint2*>(g_Xh + (size_t)row * DD);
        float s = 0.f;
#pragma unroll
        for (int j = 0; j < 4; j++) {
            int idx = lane + 32 * j;
            float4 v = x4[idx];
            xh[idx] = cvt4(v);
            s += v.x * v.x + v.y * v.y + v.z * v.z + v.w * v.w;
        }
        s = warp_sum(s);
        if (lane == 0) {
            g_a0[row] = 1.f + s;
            g_rr[row] = 2.f / (1.f - s);
        }
    } else {
        int o = bid - 2048;
        __shared__ double sp2[4];
        __shared__ float spa[4], sa2[4];
        double p2 = 0.0;
        float pa = 0.f, a2 = 0.f;
        if (tid < 128) {
            const float4* p4 = reinterpret_cast<const float4*>(P + (size_t)o * DD);
            const float4* a4 = reinterpret_cast<const float4*>(A + (size_t)o * DD);
            uint2* ph = reinterpret_cast<uint2*>(g_Ph + (size_t)o * DD);
            uint2* ah = reinterpret_cast<uint2*>(g_Ah + (size_t)o * DD);
            float4 pv = p4[tid];
            float4 av = a4[tid];
            ph[tid] = cvt4(pv);
            ah[tid] = cvt4(av);
            p2 = (double)pv.x * pv.x + (double)pv.y * pv.y +
                 (double)pv.z * pv.z + (double)pv.w * pv.w;
            pa = pv.x * av.x + pv.y * av.y + pv.z * av.z + pv.w * av.w;
            a2 = av.x * av.x + av.y * av.y + av.z * av.z + av.w * av.w;
            p2 = warp_sum_d(p2);
            pa = warp_sum(pa);
            a2 = warp_sum(a2);
            if (lane == 0) { sp2[wid] = p2; spa[wid] = pa; sa2[wid] = a2; }
        }
        __syncthreads();
        if (tid == 0) {
            double tp2 = sp2[0] + sp2[1] + sp2[2] + sp2[3];
            float tpa = spa[0] + spa[1] + spa[2] + spa[3];
            float ta2 = sa2[0] + sa2[1] + sa2[2] + sa2[3];
            double B = 1.0 - tp2;    // catastrophic cancellation handled in fp64
            double an = sqrt((double)ta2);
            if (an < (double)MINN) an = (double)MINN;
            g_B[o] = (float)B;
            g_pa[o] = tpa;
            g_q[o] = (float)(1.0 / (B * an));
            g_e2[o] = 0.69314718055994530942f * expf(S[o]);
        }
    }
}

// ---------------- PTX helpers ----------------
#define MMA_F16(d, a, b0, b1)                                                  \
    asm volatile(                                                              \
        "mma.sync.aligned.m16n8k16.row.col.f32.f16.f16.f32 "                   \
        "{%0,%1,%2,%3}, {%4,%5,%6,%7}, {%8,%9}, {%0,%1,%2,%3};"                \
        : "+f"((d)[0]), "+f"((d)[1]), "+f"((d)[2]), "+f"((d)[3])               \
        : "r"((a)[0]), "r"((a)[1]), "r"((a)[2]), "r"((a)[3]), "r"(b0), "r"(b1))

#define LDMX4(r, addr)                                                         \
    asm volatile("ldmatrix.sync.aligned.m8n8.x4.shared.b16 {%0,%1,%2,%3}, [%4];" \
                 : "=r"((r)[0]), "=r"((r)[1]), "=r"((r)[2]), "=r"((r)[3])      \
                 : "r"(addr))

#define CPA16(saddr, gptr)                                                     \
    asm volatile("cp.async.cg.shared.global [%0], [%1], 16;"                   \
                 :: "r"(saddr), "l"(gptr))
#define CPA_COMMIT() asm volatile("cp.async.commit_group;" ::: "memory")
#define CPA_WAIT2() asm volatile("cp.async.wait_group 2;" ::: "memory")

// asinh(arg)*e^s: asinh t = ln(t+sqrt(t^2+1)) = lg2(.)*ln2.
// Fast path (warp-uniform): all lanes |t| >= 64 -> asinh(t) ~= ln(2t).
__device__ __forceinline__ float epi(float xp, float xa, float a0, float rr,
                                     float B, float pa, float q, float e2) {
    float Aa = fmaf(-2.f, xp, a0);      // A = 1 + x^2 - 2*xp
    float tn = fmaf(B, xa, -Aa * pa);   // B*xa - A*pa
    float arg = tn * rr * q;            // 2*tn / (B*(1-x^2)*||a||)
    float tt = fabsf(arg);
    float u;
    if (__any_sync(0xffffffffu, tt < 64.f)) {
        float s;
        asm("sqrt.approx.f32 %0, %1;" : "=f"(s) : "f"(fmaf(tt, tt, 1.f)));
        u = tt + s;
    } else {
        u = tt + tt;
    }
    float r;
    asm("lg2.approx.f32 %0, %1;" : "=f"(r) : "f"(u));
    return copysignf(r * e2, arg);
}

// ---------------- main: fp16 mma.sync dual-GEMM + analytic Mobius epilogue ----
// 64x64 block tile, 256 threads, warp grid 2(M) x 4(N), warp tile 32x16.
// 4-stage cp.async pipeline (prefetch distance 3), ldmatrix + frag double-buffer.
// grid = 2048 CTAs -> 6.92 waves at 296 concurrent CTAs (98.8% quantization).
__global__ void __launch_bounds__(256, 2) mobius_main(float* __restrict__ out) {
    extern __shared__ __half smh[];
    int tid = threadIdx.x;
    int lane = tid & 31, wid = tid >> 5;
    int wm = wid & 1, wn = wid >> 1;
    int m0 = blockIdx.y * BM, n0 = blockIdx.x * BN;

    const __half* Xg = g_Xh + (size_t)m0 * DD;
    const __half* Pg = g_Ph + (size_t)n0 * DD;
    const __half* Ag = g_Ah + (size_t)n0 * DD;
    uint32_t sbase = (uint32_t)__cvta_generic_to_shared(smh);

// 512 16B-chunks per matrix per stage (64 rows x 8 chunks); 2 per thread each.
#define LOAD_STAGE(stg, kt)                                                    \
    {                                                                          \
        uint32_t st = sbase + (uint32_t)(stg) * (STAGE_H * 2);                 \
        int k0 = (kt) * BK;                                                    \
        _Pragma("unroll") for (int j = 0; j < 2; j++) {                        \
            int f = tid + 256 * j;                                             \
            int row = f >> 3, ck = f & 7;                                      \
            uint32_t so = (uint32_t)(row * (LH * 2) + ck * 16);                \
            size_t go = (size_t)row * DD + k0 + ck * 8;                        \
            CPA16(st + so, Xg + go);                                           \
            CPA16(st + TXH * 2 + so, Pg + go);                                 \
            CPA16(st + (TXH + TBH) * 2 + so, Ag + go);                         \
        }                                                                      \
    }

    float accP[2][2][4];
    float accA[2][2][4];
#pragma unroll
    for (int mt = 0; mt < 2; mt++)
#pragma unroll
        for (int nt = 0; nt < 2; nt++)
#pragma unroll
            for (int e = 0; e < 4; e++) { accP[mt][nt][e] = 0.f; accA[mt][nt][e] = 0.f; }

    LOAD_STAGE(0, 0); CPA_COMMIT();
    LOAD_STAGE(1, 1); CPA_COMMIT();
    LOAD_STAGE(2, 2); CPA_COMMIT();

    // ldmatrix per-lane base addresses (bytes, within a stage)
    // A (x tile): lanes 0-15 -> m rows k0 | 16-31 -> m rows k8
    uint32_t a_base = (uint32_t)(((wm * 32 + (lane & 15)) * LH + ((lane >> 4) << 3)) * 2);
    // B (p/a tiles): lanes 0-7 n0-7 k0 | 8-15 n0-7 k8 | 16-23 n8-15 k0 | 24-31 n8-15 k8
    uint32_t b_row = (uint32_t)(wn * 16 + (((lane >> 4) & 1) << 3) + (lane & 7));
    uint32_t b_base = (uint32_t)((b_row * LH + (((lane >> 3) & 1) << 3)) * 2);

    for (int c = 0; c < NKT; ++c) {
        CPA_WAIT2();
        __syncthreads();
        if (c + 3 < NKT) { LOAD_STAGE((c + 3) & 3, c + 3); }
        CPA_COMMIT();

        uint32_t st = sbase + (uint32_t)(c & 3) * (STAGE_H * 2);
        uint32_t aA = st + a_base;
        uint32_t aP = st + TXH * 2 + b_base;
        uint32_t aT = aP + TBH * 2;

        // register double-buffered fragments across ks
        uint32_t af[2][2][4], bp[2][4], ba[2][4];
#pragma unroll
        for (int mt = 0; mt < 2; mt++)
            LDMX4(af[0][mt], aA + (uint32_t)(mt * 16 * LH * 2));
        LDMX4(bp[0], aP);
        LDMX4(ba[0], aT);

#pragma unroll
        for (int ks = 0; ks < 4; ks++) {    // 4 x k16 per k-tile of 64
            int cur = ks & 1, nxt = cur ^ 1;
            if (ks < 3) {
#pragma unroll
                for (int mt = 0; mt < 2; mt++)
                    LDMX4(af[nxt][mt],
                          aA + (uint32_t)(mt * 16 * LH * 2 + (ks + 1) * 32));
                LDMX4(bp[nxt], aP + (uint32_t)((ks + 1) * 32));
                LDMX4(ba[nxt], aT + (uint32_t)((ks + 1) * 32));
            }
#pragma unroll
            for (int nt = 0; nt < 2; nt++) {
#pragma unroll
                for (int mt = 0; mt < 2; mt++) {
                    MMA_F16(accP[mt][nt], af[cur][mt], bp[cur][2 * nt], bp[cur][2 * nt + 1]);
                    MMA_F16(accA[mt][nt], af[cur][mt], ba[cur][2 * nt], ba[cur][2 * nt + 1]);
                }
            }
        }
    }

    // ---- epilogue ----
    int g = lane >> 2, t = lane & 3;
    float a0r[2][2], rrr[2][2];
#pragma unroll
    for (int mt = 0; mt < 2; mt++)
#pragma unroll
        for (int h = 0; h < 2; h++) {
            int r = m0 + wm * 32 + mt * 16 + g + h * 8;
            a0r[mt][h] = g_a0[r];
            rrr[mt][h] = g_rr[r];
        }
    float Bc[2][2], pac[2][2], qc[2][2], e2c[2][2];
#pragma unroll
    for (int nt = 0; nt < 2; nt++)
#pragma unroll
        for (int w = 0; w < 2; w++) {
            int cc = n0 + wn * 16 + nt * 8 + 2 * t + w;
            Bc[nt][w] = g_B[cc];
            pac[nt][w] = g_pa[cc];
            qc[nt][w] = g_q[cc];
            e2c[nt][w] = g_e2[cc];
        }
#pragma unroll
    for (int mt = 0; mt < 2; mt++) {
#pragma unroll
        for (int h = 0; h < 2; h++) {
            int r = m0 + wm * 32 + mt * 16 + g + h * 8;
            float* orow = out + (size_t)r * OO + n0 + wn * 16 + 2 * t;
#pragma unroll
            for (int nt = 0; nt < 2; nt++) {
                float o0 = epi(accP[mt][nt][h * 2 + 0], accA[mt][nt][h * 2 + 0],
                               a0r[mt][h], rrr[mt][h],
                               Bc[nt][0], pac[nt][0], qc[nt][0], e2c[nt][0]);
                float o1 = epi(accP[mt][nt][h * 2 + 1], accA[mt][nt][h * 2 + 1],
                               a0r[mt][h], rrr[mt][h],
                               Bc[nt][1], pac[nt][1], qc[nt][1], e2c[nt][1]);
                *reinterpret_cast<float2*>(orow + nt * 8) = make_float2(o0, o1);
            }
        }
    }
}

extern "C" void kernel_launch(void* const* d_in, const int* in_sizes, int n_in,
                              void* d_out, int out_size) {
    const float* x = (const float*)d_in[0];      // [N, D]
    const float* p = (const float*)d_in[1];      // [O, D]
    const float* a = (const float*)d_in[2];      // [O, D]
    const float* s = (const float*)d_in[3];      // [O]
    float* out = (float*)d_out;                  // [N, O]

    prep<<<2048 + OO, 256>>>(x, p, a, s);
    cudaFuncSetAttribute(mobius_main, cudaFuncAttributeMaxDynamicSharedMemorySize,
                         SMEM_BYTES);
    dim3 grid(OO / BN, NN / BM);
    mobius_main<<<grid, 256, SMEM_BYTES>>>(out);
}

// round 11
// speedup vs baseline: 1.0516x; 1.0516x over previous
#include <cuda_runtime.h>
#include <cuda_fp16.h>
#include <math.h>
#include <cstdint>

#define NN 16384
#define DD 512
#define OO 512
#define BM 128
#define BN 64
#define BK 64                   // k-tile in elements (fp16)
#define NKT (DD / BK)           // 8 k-tiles
#define LH 72                   // smem fp16 per row (144B) -> conflict-free ldmatrix
#define TXH (BM * LH)           // 9216 halfs, X tile
#define TBH (BN * LH)           // 4608 halfs, P or A tile
#define STAGE_H (TXH + 2 * TBH) // 18432 halfs = 36864 B
#define SMEM_BYTES (3 * STAGE_H * 2)  // 110592 B, 3 stages -> 2 CTAs/SM
#define MINN 1e-15f

// Precomputed stats + fp16 operand copies (no allocations -> device globals).
__device__ float g_a0[NN];    // 1 + ||x||^2
__device__ float g_rr[NN];    // 2 / (1 - ||x||^2)
__device__ float g_B[OO];     // 1 - ||p||^2   (fp64-accurate)
__device__ float g_pa[OO];    // <p, a>
__device__ float g_q[OO];     // 1 / (B * ||a||)
__device__ float g_e2[OO];    // ln(2) * exp(scale)
__device__ __half g_Xh[NN * DD];
__device__ __half g_Ph[OO * DD];
__device__ __half g_Ah[OO * DD];

__device__ __forceinline__ float warp_sum(float v) {
#pragma unroll
    for (int s = 16; s > 0; s >>= 1) v += __shfl_xor_sync(0xffffffffu, v, s);
    return v;
}
__device__ __forceinline__ double warp_sum_d(double v) {
#pragma unroll
    for (int s = 16; s > 0; s >>= 1) v += __shfl_xor_sync(0xffffffffu, v, s);
    return v;
}
__device__ __forceinline__ uint2 cvt4(float4 v) {
    __half2 h0 = __floats2half2_rn(v.x, v.y);
    __half2 h1 = __floats2half2_rn(v.z, v.w);
    uint2 u;
    u.x = *reinterpret_cast<uint32_t*>(&h0);
    u.y = *reinterpret_cast<uint32_t*>(&h1);
    return u;
}

// ---------------- fused prep: X convert + x-stats | P/A convert + o-stats ----
__global__ void prep(const float* __restrict__ X, const float* __restrict__ P,
                     const float* __restrict__ A, const float* __restrict__ S) {
    int bid = blockIdx.x;
    int tid = threadIdx.x;
    int wid = tid >> 5, lane = tid & 31;
    if (bid < 2048) {
        int row = bid * 8 + wid;
        const float4* x4 = reinterpret_cast<const float4*>(X + (size_t)row * DD);
        uint2* xh = reinterpret_cast<uint2*>(g_Xh + (size_t)row * DD);
        float s = 0.f;
#pragma unroll
        for (int j = 0; j < 4; j++) {
            int idx = lane + 32 * j;
            float4 v = x4[idx];
            xh[idx] = cvt4(v);
            s += v.x * v.x + v.y * v.y + v.z * v.z + v.w * v.w;
        }
        s = warp_sum(s);
        if (lane == 0) {
            g_a0[row] = 1.f + s;
            g_rr[row] = 2.f / (1.f - s);
        }
    } else {
        int o = bid - 2048;
        __shared__ double sp2[4];
        __shared__ float spa[4], sa2[4];
        double p2 = 0.0;
        float pa = 0.f, a2 = 0.f;
        if (tid < 128) {
            const float4* p4 = reinterpret_cast<const float4*>(P + (size_t)o * DD);
            const float4* a4 = reinterpret_cast<const float4*>(A + (size_t)o * DD);
            uint2* ph = reinterpret_cast<uint2*>(g_Ph + (size_t)o * DD);
            uint2* ah = reinterpret_cast<uint2*>(g_Ah + (size_t)o * DD);
            float4 pv = p4[tid];
            float4 av = a4[tid];
            ph[tid] = cvt4(pv);
            ah[tid] = cvt4(av);
            p2 = (double)pv.x * pv.x + (double)pv.y * pv.y +
                 (double)pv.z * pv.z + (double)pv.w * pv.w;
            pa = pv.x * av.x + pv.y * av.y + pv.z * av.z + pv.w * av.w;
            a2 = av.x * av.x + av.y * av.y + av.z * av.z + av.w * av.w;
            p2 = warp_sum_d(p2);
            pa = warp_sum(pa);
            a2 = warp_sum(a2);
            if (lane == 0) { sp2[wid] = p2; spa[wid] = pa; sa2[wid] = a2; }
        }
        __syncthreads();
        if (tid == 0) {
            double tp2 = sp2[0] + sp2[1] + sp2[2] + sp2[3];
            float tpa = spa[0] + spa[1] + spa[2] + spa[3];
            float ta2 = sa2[0] + sa2[1] + sa2[2] + sa2[3];
            double B = 1.0 - tp2;    // catastrophic cancellation handled in fp64
            double an = sqrt((double)ta2);
            if (an < (double)MINN) an = (double)MINN;
            g_B[o] = (float)B;
            g_pa[o] = tpa;
            g_q[o] = (float)(1.0 / (B * an));
            g_e2[o] = 0.69314718055994530942f * expf(S[o]);
        }
    }
}

// ---------------- PTX helpers ----------------
// fp16-accumulate MMA: full-rate HMMA path. D,C are 2x b32 (4 halfs).
#define MMA_F16H(d, a, b0, b1)                                                 \
    asm volatile(                                                              \
        "mma.sync.aligned.m16n8k16.row.col.f16.f16.f16.f16 "                   \
        "{%0,%1}, {%2,%3,%4,%5}, {%6,%7}, {%0,%1};"                            \
        : "+r"((d)[0]), "+r"((d)[1])                                           \
        : "r"((a)[0]), "r"((a)[1]), "r"((a)[2]), "r"((a)[3]), "r"(b0), "r"(b1))

#define LDMX4(r, addr)                                                         \
    asm volatile("ldmatrix.sync.aligned.m8n8.x4.shared.b16 {%0,%1,%2,%3}, [%4];" \
                 : "=r"((r)[0]), "=r"((r)[1]), "=r"((r)[2]), "=r"((r)[3])      \
                 : "r"(addr))

#define CPA16(saddr, gptr)                                                     \
    asm volatile("cp.async.cg.shared.global [%0], [%1], 16;"                   \
                 :: "r"(saddr), "l"(gptr))
#define CPA_COMMIT() asm volatile("cp.async.commit_group;" ::: "memory")
#define CPA_WAIT1() asm volatile("cp.async.wait_group 1;" ::: "memory")

// asinh(arg)*e^s: asinh t = ln(t+sqrt(t^2+1)) = lg2(.)*ln2.
// Fast path (warp-uniform): all lanes |t| >= 64 -> asinh(t) ~= ln(2t).
__device__ __forceinline__ float epi(float xp, float xa, float a0, float rr,
                                     float B, float pa, float q, float e2) {
    float Aa = fmaf(-2.f, xp, a0);      // A = 1 + x^2 - 2*xp
    float tn = fmaf(B, xa, -Aa * pa);   // B*xa - A*pa
    float arg = tn * rr * q;            // 2*tn / (B*(1-x^2)*||a||)
    float tt = fabsf(arg);
    float u;
    if (__any_sync(0xffffffffu, tt < 64.f)) {
        float s;
        asm("sqrt.approx.f32 %0, %1;" : "=f"(s) : "f"(fmaf(tt, tt, 1.f)));
        u = tt + s;
    } else {
        u = tt + tt;
    }
    float r;
    asm("lg2.approx.f32 %0, %1;" : "=f"(r) : "f"(u));
    return copysignf(r * e2, arg);
}

// ---------------- main: fp16 mma.sync dual-GEMM + analytic Mobius epilogue ----
// 128x64 block tile, 256 threads, warp grid 2(M) x 4(N), warp tile 64x16.
// 3-stage cp.async pipeline, ldmatrix + frag double-buffer, FP16 ACCUMULATORS.
__global__ void __launch_bounds__(256, 2) mobius_main(float* __restrict__ out) {
    extern __shared__ __half smh[];
    int tid = threadIdx.x;
    int lane = tid & 31, wid = tid >> 5;
    int wm = wid & 1, wn = wid >> 1;
    int m0 = blockIdx.y * BM, n0 = blockIdx.x * BN;

    const __half* Xg = g_Xh + (size_t)m0 * DD;
    const __half* Pg = g_Ph + (size_t)n0 * DD;
    const __half* Ag = g_Ah + (size_t)n0 * DD;
    uint32_t sbase = (uint32_t)__cvta_generic_to_shared(smh);

#define LOAD_STAGE(stg, kt)                                                    \
    {                                                                          \
        uint32_t st = sbase + (uint32_t)(stg) * (STAGE_H * 2);                 \
        int k0 = (kt) * BK;                                                    \
        _Pragma("unroll") for (int j = 0; j < 4; j++) {  /* X: 1024 chunks */  \
            int f = tid + 256 * j;                                             \
            int row = f >> 3, ck = f & 7;                                      \
            CPA16(st + (uint32_t)(row * (LH * 2) + ck * 16),                   \
                  Xg + (size_t)row * DD + k0 + ck * 8);                        \
        }                                                                      \
        _Pragma("unroll") for (int j = 0; j < 2; j++) {  /* P: 512 chunks */   \
            int f = tid + 256 * j;                                             \
            int row = f >> 3, ck = f & 7;                                      \
            CPA16(st + (uint32_t)(TXH * 2 + row * (LH * 2) + ck * 16),         \
                  Pg + (size_t)row * DD + k0 + ck * 8);                        \
        }                                                                      \
        _Pragma("unroll") for (int j = 0; j < 2; j++) {  /* A: 512 chunks */   \
            int f = tid + 256 * j;                                             \
            int row = f >> 3, ck = f & 7;                                      \
            CPA16(st + (uint32_t)((TXH + TBH) * 2 + row * (LH * 2) + ck * 16), \
                  Ag + (size_t)row * DD + k0 + ck * 8);                        \
        }                                                                      \
    }

    // fp16 accumulators: [mt][nt][h], h = row-half (g / g+8); each reg = 2 halfs
    uint32_t accP[4][2][2];
    uint32_t accA[4][2][2];
#pragma unroll
    for (int mt = 0; mt < 4; mt++)
#pragma unroll
        for (int nt = 0; nt < 2; nt++)
#pragma unroll
            for (int h = 0; h < 2; h++) { accP[mt][nt][h] = 0u; accA[mt][nt][h] = 0u; }

    LOAD_STAGE(0, 0); CPA_COMMIT();
    LOAD_STAGE(1, 1); CPA_COMMIT();

    // ldmatrix per-lane base addresses (bytes, within a stage)
    uint32_t a_base = (uint32_t)(((wm * 64 + (lane & 15)) * LH + ((lane >> 4) << 3)) * 2);
    uint32_t b_row = (uint32_t)(wn * 16 + (((lane >> 4) & 1) << 3) + (lane & 7));
    uint32_t b_base = (uint32_t)((b_row * LH + (((lane >> 3) & 1) << 3)) * 2);

    for (int c = 0; c < NKT; ++c) {
        CPA_WAIT1();
        __syncthreads();
        if (c + 2 < NKT) { LOAD_STAGE((c + 2) % 3, c + 2); }
        CPA_COMMIT();

        uint32_t st = sbase + (uint32_t)(c % 3) * (STAGE_H * 2);
        uint32_t aA = st + a_base;
        uint32_t aP = st + TXH * 2 + b_base;
        uint32_t aT = aP + TBH * 2;

        // register double-buffered fragments across ks
        uint32_t af[2][4][4], bp[2][4], ba[2][4];
#pragma unroll
        for (int mt = 0; mt < 4; mt++)
            LDMX4(af[0][mt], aA + (uint32_t)(mt * 16 * LH * 2));
        LDMX4(bp[0], aP);
        LDMX4(ba[0], aT);

#pragma unroll
        for (int ks = 0; ks < 4; ks++) {    // 4 x k16 per k-tile of 64
            int cur = ks & 1, nxt = cur ^ 1;
            if (ks < 3) {
#pragma unroll
                for (int mt = 0; mt < 4; mt++)
                    LDMX4(af[nxt][mt],
                          aA + (uint32_t)(mt * 16 * LH * 2 + (ks + 1) * 32));
                LDMX4(bp[nxt], aP + (uint32_t)((ks + 1) * 32));
                LDMX4(ba[nxt], aT + (uint32_t)((ks + 1) * 32));
            }
#pragma unroll
            for (int nt = 0; nt < 2; nt++) {
#pragma unroll
                for (int mt = 0; mt < 4; mt++) {
                    MMA_F16H(accP[mt][nt], af[cur][mt], bp[cur][2 * nt], bp[cur][2 * nt + 1]);
                    MMA_F16H(accA[mt][nt], af[cur][mt], ba[cur][2 * nt], ba[cur][2 * nt + 1]);
                }
            }
        }
    }

    // ---- epilogue ----
    int g = lane >> 2, t = lane & 3;
    float a0r[4][2], rrr[4][2];
#pragma unroll
    for (int mt = 0; mt < 4; mt++)
#pragma unroll
        for (int h = 0; h < 2; h++) {
            int r = m0 + wm * 64 + mt * 16 + g + h * 8;
            a0r[mt][h] = g_a0[r];
            rrr[mt][h] = g_rr[r];
        }
    float Bc[2][2], pac[2][2], qc[2][2], e2c[2][2];
#pragma unroll
    for (int nt = 0; nt < 2; nt++)
#pragma unroll
        for (int w = 0; w < 2; w++) {
            int cc = n0 + wn * 16 + nt * 8 + 2 * t + w;
            Bc[nt][w] = g_B[cc];
            pac[nt][w] = g_pa[cc];
            qc[nt][w] = g_q[cc];
            e2c[nt][w] = g_e2[cc];
        }
#pragma unroll
    for (int mt = 0; mt < 4; mt++) {
#pragma unroll
        for (int h = 0; h < 2; h++) {
            int r = m0 + wm * 64 + mt * 16 + g + h * 8;
            float* orow = out + (size_t)r * OO + n0 + wn * 16 + 2 * t;
#pragma unroll
            for (int nt = 0; nt < 2; nt++) {
                float2 vP = __half22float2(
                    *reinterpret_cast<__half2*>(&accP[mt][nt][h]));
                float2 vA = __half22float2(
                    *reinterpret_cast<__half2*>(&accA[mt][nt][h]));
                float o0 = epi(vP.x, vA.x, a0r[mt][h], rrr[mt][h],
                               Bc[nt][0], pac[nt][0], qc[nt][0], e2c[nt][0]);
                float o1 = epi(vP.y, vA.y, a0r[mt][h], rrr[mt][h],
                               Bc[nt][1], pac[nt][1], qc[nt][1], e2c[nt][1]);
                *reinterpret_cast<float2*>(orow + nt * 8) = make_float2(o0, o1);
            }
        }
    }
}

extern "C" void kernel_launch(void* const* d_in, const int* in_sizes, int n_in,
                              void* d_out, int out_size) {
    const float* x = (const float*)d_in[0];      // [N, D]
    const float* p = (const float*)d_in[1];      // [O, D]
    const float* a = (const float*)d_in[2];      // [O, D]
    const float* s = (const float*)d_in[3];      // [O]
    float* out = (float*)d_out;                  // [N, O]

    prep<<<2048 + OO, 256>>>(x, p, a, s);
    cudaFuncSetAttribute(mobius_main, cudaFuncAttributeMaxDynamicSharedMemorySize,
                         SMEM_BYTES);
    dim3 grid(OO / BN, NN / BM);
    mobius_main<<<grid, 256, SMEM_BYTES>>>(out);
}

// round 12
// speedup vs baseline: 1.3671x; 1.3001x over previous
#include <cuda_runtime.h>
#include <cuda_fp16.h>
#include <math.h>
#include <cstdint>

#define NN 16384
#define DD 512
#define OO 512
#define BM 128
#define BN 128
#define BK 64                   // k-tile in elements (fp16)
#define NKT (DD / BK)           // 8 k-tiles
#define LH 72                   // smem fp16 per row (144B) -> conflict-free ldmatrix
#define TXH (BM * LH)           // 9216 halfs, X tile
#define TCH (BN * LH)           // 9216 halfs, C tile
#define STAGE_H (TXH + TCH)     // 18432 halfs = 36864 B
#define SMEM_BYTES (3 * STAGE_H * 2)  // 110592 B, 3 stages -> 2 CTAs/SM
#define MINN 1e-15f

// Precomputed stats + fp16 operands (no allocations -> device globals).
__device__ float g_a0[NN];    // 1 + ||x||^2
__device__ float g_rr[NN];    // 2 / (1 - ||x||^2)
__device__ float g_paq[OO];   // <p,a> / (B * ||a||)   (B = 1-||p||^2 in fp64)
__device__ float g_ran[OO];   // 1 / ||a||
__device__ float g_e2[OO];    // ln(2) * exp(scale)
__device__ __half g_Xh[NN * DD];
__device__ __half g_Ch[OO * DD];   // c = a/||a|| + 2*paq*p

__device__ __forceinline__ float warp_sum(float v) {
#pragma unroll
    for (int s = 16; s > 0; s >>= 1) v += __shfl_xor_sync(0xffffffffu, v, s);
    return v;
}
__device__ __forceinline__ double warp_sum_d(double v) {
#pragma unroll
    for (int s = 16; s > 0; s >>= 1) v += __shfl_xor_sync(0xffffffffu, v, s);
    return v;
}
__device__ __forceinline__ uint2 cvt4(float4 v) {
    __half2 h0 = __floats2half2_rn(v.x, v.y);
    __half2 h1 = __floats2half2_rn(v.z, v.w);
    uint2 u;
    u.x = *reinterpret_cast<uint32_t*>(&h0);
    u.y = *reinterpret_cast<uint32_t*>(&h1);
    return u;
}

// ---------------- prep1: X convert + x-stats | o-stats (B fp64, paq, e2) ------
__global__ void prep(const float* __restrict__ X, const float* __restrict__ P,
                     const float* __restrict__ A, const float* __restrict__ S) {
    int bid = blockIdx.x;
    int tid = threadIdx.x;
    int wid = tid >> 5, lane = tid & 31;
    if (bid < 2048) {
        int row = bid * 8 + wid;
        const float4* x4 = reinterpret_cast<const float4*>(X + (size_t)row * DD);
        uint2* xh = reinterpret_cast<uint2*>(g_Xh + (size_t)row * DD);
        float s = 0.f;
#pragma unroll
        for (int j = 0; j < 4; j++) {
            int idx = lane + 32 * j;
            float4 v = x4[idx];
            xh[idx] = cvt4(v);
            s += v.x * v.x + v.y * v.y + v.z * v.z + v.w * v.w;
        }
        s = warp_sum(s);
        if (lane == 0) {
            g_a0[row] = 1.f + s;
            g_rr[row] = 2.f / (1.f - s);
        }
    } else {
        int o = bid - 2048;
        __shared__ double sp2[4];
        __shared__ float spa[4], sa2[4];
        if (tid < 128) {
            const float4* p4 = reinterpret_cast<const float4*>(P + (size_t)o * DD);
            const float4* a4 = reinterpret_cast<const float4*>(A + (size_t)o * DD);
            float4 pv = p4[tid];
            float4 av = a4[tid];
            double p2 = (double)pv.x * pv.x + (double)pv.y * pv.y +
                        (double)pv.z * pv.z + (double)pv.w * pv.w;
            float pa = pv.x * av.x + pv.y * av.y + pv.z * av.z + pv.w * av.w;
            float a2 = av.x * av.x + av.y * av.y + av.z * av.z + av.w * av.w;
            p2 = warp_sum_d(p2);
            pa = warp_sum(pa);
            a2 = warp_sum(a2);
            if (lane == 0) { sp2[wid] = p2; spa[wid] = pa; sa2[wid] = a2; }
        }
        __syncthreads();
        if (tid == 0) {
            double tp2 = sp2[0] + sp2[1] + sp2[2] + sp2[3];
            double tpa = (double)spa[0] + spa[1] + spa[2] + spa[3];
            double ta2 = (double)sa2[0] + sa2[1] + sa2[2] + sa2[3];
            double B = 1.0 - tp2;    // catastrophic cancellation handled in fp64
            double an = sqrt(ta2);
            if (an < (double)MINN) an = (double)MINN;
            g_paq[o] = (float)(tpa / (B * an));
            g_ran[o] = (float)(1.0 / an);
            g_e2[o] = 0.69314718055994530942f * expf(S[o]);
        }
    }
}

// ---------------- prep2: build fused operand c = a/||a|| + 2*paq*p ------------
__global__ void build_c(const float* __restrict__ P, const float* __restrict__ A) {
    int o = blockIdx.x;
    int tid = threadIdx.x;   // 128 threads, one float4 each
    float paq2 = 2.f * g_paq[o];
    float ran = g_ran[o];
    const float4* p4 = reinterpret_cast<const float4*>(P + (size_t)o * DD);
    const float4* a4 = reinterpret_cast<const float4*>(A + (size_t)o * DD);
    uint2* ch = reinterpret_cast<uint2*>(g_Ch + (size_t)o * DD);
    float4 pv = p4[tid];
    float4 av = a4[tid];
    float4 c;
    c.x = fmaf(paq2, pv.x, av.x * ran);
    c.y = fmaf(paq2, pv.y, av.y * ran);
    c.z = fmaf(paq2, pv.z, av.z * ran);
    c.w = fmaf(paq2, pv.w, av.w * ran);
    ch[tid] = cvt4(c);
}

// ---------------- PTX helpers ----------------
#define MMA_F16(d, a, b0, b1)                                                  \
    asm volatile(                                                              \
        "mma.sync.aligned.m16n8k16.row.col.f32.f16.f16.f32 "                   \
        "{%0,%1,%2,%3}, {%4,%5,%6,%7}, {%8,%9}, {%0,%1,%2,%3};"                \
        : "+f"((d)[0]), "+f"((d)[1]), "+f"((d)[2]), "+f"((d)[3])               \
        : "r"((a)[0]), "r"((a)[1]), "r"((a)[2]), "r"((a)[3]), "r"(b0), "r"(b1))

#define LDMX4(r, addr)                                                         \
    asm volatile("ldmatrix.sync.aligned.m8n8.x4.shared.b16 {%0,%1,%2,%3}, [%4];" \
                 : "=r"((r)[0]), "=r"((r)[1]), "=r"((r)[2]), "=r"((r)[3])      \
                 : "r"(addr))

#define CPA16(saddr, gptr)                                                     \
    asm volatile("cp.async.cg.shared.global [%0], [%1], 16;"                   \
                 :: "r"(saddr), "l"(gptr))
#define CPA_COMMIT() asm volatile("cp.async.commit_group;" ::: "memory")
#define CPA_WAIT1() asm volatile("cp.async.wait_group 1;" ::: "memory")

// asinh(arg)*e^s: asinh t = ln(t+sqrt(t^2+1)) = lg2(.)*ln2.
// Fast path (warp-uniform): all lanes |t| >= 64 -> asinh(t) ~= ln(2t).
__device__ __forceinline__ float epi(float xc, float a0, float rr,
                                     float paq, float e2) {
    float arg = (xc - a0 * paq) * rr;
    float tt = fabsf(arg);
    float u;
    if (__any_sync(0xffffffffu, tt < 64.f)) {
        float s;
        asm("sqrt.approx.f32 %0, %1;" : "=f"(s) : "f"(fmaf(tt, tt, 1.f)));
        u = tt + s;
    } else {
        u = tt + tt;
    }
    float r;
    asm("lg2.approx.f32 %0, %1;" : "=f"(r) : "f"(u));
    return copysignf(r * e2, arg);
}

// ---------------- main: SINGLE fp16 GEMM (x @ c^T) + tiny epilogue -----------
// 128x128 block tile, 256 threads, warp grid 2(M) x 4(N), warp tile 64x32.
__global__ void __launch_bounds__(256, 2) mobius_main(float* __restrict__ out) {
    extern __shared__ __half smh[];
    int tid = threadIdx.x;
    int lane = tid & 31, wid = tid >> 5;
    int wm = wid & 1, wn = wid >> 1;
    int m0 = blockIdx.y * BM, n0 = blockIdx.x * BN;

    const __half* Xg = g_Xh + (size_t)m0 * DD;
    const __half* Cg = g_Ch + (size_t)n0 * DD;
    uint32_t sbase = (uint32_t)__cvta_generic_to_shared(smh);

#define LOAD_STAGE(stg, kt)                                                    \
    {                                                                          \
        uint32_t st = sbase + (uint32_t)(stg) * (STAGE_H * 2);                 \
        int k0 = (kt) * BK;                                                    \
        _Pragma("unroll") for (int j = 0; j < 4; j++) {  /* 1024 chunks ea */  \
            int f = tid + 256 * j;                                             \
            int row = f >> 3, ck = f & 7;                                      \
            uint32_t so = (uint32_t)(row * (LH * 2) + ck * 16);                \
            size_t go = (size_t)row * DD + k0 + ck * 8;                        \
            CPA16(st + so, Xg + go);                                           \
            CPA16(st + TXH * 2 + so, Cg + go);                                 \
        }                                                                      \
    }

    float acc[4][4][4];
#pragma unroll
    for (int mt = 0; mt < 4; mt++)
#pragma unroll
        for (int nt = 0; nt < 4; nt++)
#pragma unroll
            for (int e = 0; e < 4; e++) acc[mt][nt][e] = 0.f;

    LOAD_STAGE(0, 0); CPA_COMMIT();
    LOAD_STAGE(1, 1); CPA_COMMIT();

    // ldmatrix per-lane base addresses (bytes, within a stage)
    // A (x tile): lanes 0-15 -> m rows, k0 | 16-31 -> m rows, k8
    uint32_t a_base = (uint32_t)(((wm * 64 + (lane & 15)) * LH + ((lane >> 4) << 3)) * 2);
    // B (c tile): lanes 0-7 n0-7 k0 | 8-15 n0-7 k8 | 16-23 n8-15 k0 | 24-31 n8-15 k8
    uint32_t b_row = (uint32_t)(wn * 32 + (((lane >> 4) & 1) << 3) + (lane & 7));
    uint32_t b_base = (uint32_t)((b_row * LH + (((lane >> 3) & 1) << 3)) * 2);

    for (int c = 0; c < NKT; ++c) {
        CPA_WAIT1();
        __syncthreads();
        if (c + 2 < NKT) { LOAD_STAGE((c + 2) % 3, c + 2); }
        CPA_COMMIT();

        uint32_t st = sbase + (uint32_t)(c % 3) * (STAGE_H * 2);
        uint32_t aA = st + a_base;
        uint32_t aC = st + TXH * 2 + b_base;
#pragma unroll
        for (int ks = 0; ks < 4; ks++) {    // 4 x k16 per k-tile of 64
            uint32_t af[4][4], bc[2][4];
#pragma unroll
            for (int mt = 0; mt < 4; mt++)
                LDMX4(af[mt], aA + (uint32_t)(mt * 16 * LH * 2 + ks * 32));
            LDMX4(bc[0], aC + (uint32_t)(ks * 32));
            LDMX4(bc[1], aC + (uint32_t)(16 * LH * 2 + ks * 32));
#pragma unroll
            for (int nt = 0; nt < 4; nt++) {
                uint32_t b0 = bc[nt >> 1][2 * (nt & 1)];
                uint32_t b1 = bc[nt >> 1][2 * (nt & 1) + 1];
#pragma unroll
                for (int mt = 0; mt < 4; mt++)
                    MMA_F16(acc[mt][nt], af[mt], b0, b1);
            }
        }
    }

    // ---- epilogue: arg = (xc - a0*paq)*rr; dist = asinh(arg)*e^s ----
    int g = lane >> 2, t = lane & 3;
    float a0r[4][2], rrr[4][2];
#pragma unroll
    for (int mt = 0; mt < 4; mt++)
#pragma unroll
        for (int h = 0; h < 2; h++) {
            int r = m0 + wm * 64 + mt * 16 + g + h * 8;
            a0r[mt][h] = g_a0[r];
            rrr[mt][h] = g_rr[r];
        }
    float paqc[4][2], e2c[4][2];
#pragma unroll
    for (int nt = 0; nt < 4; nt++)
#pragma unroll
        for (int w = 0; w < 2; w++) {
            int cc = n0 + wn * 32 + nt * 8 + 2 * t + w;
            paqc[nt][w] = g_paq[cc];
            e2c[nt][w] = g_e2[cc];
        }
#pragma unroll
    for (int mt = 0; mt < 4; mt++) {
#pragma unroll
        for (int h = 0; h < 2; h++) {
            int r = m0 + wm * 64 + mt * 16 + g + h * 8;
            float* orow = out + (size_t)r * OO + n0 + wn * 32 + 2 * t;
#pragma unroll
            for (int nt = 0; nt < 4; nt++) {
                float o0 = epi(acc[mt][nt][h * 2 + 0], a0r[mt][h], rrr[mt][h],
                               paqc[nt][0], e2c[nt][0]);
                float o1 = epi(acc[mt][nt][h * 2 + 1], a0r[mt][h], rrr[mt][h],
                               paqc[nt][1], e2c[nt][1]);
                *reinterpret_cast<float2*>(orow + nt * 8) = make_float2(o0, o1);
            }
        }
    }
}

extern "C" void kernel_launch(void* const* d_in, const int* in_sizes, int n_in,
                              void* d_out, int out_size) {
    const float* x = (const float*)d_in[0];      // [N, D]
    const float* p = (const float*)d_in[1];      // [O, D]
    const float* a = (const float*)d_in[2];      // [O, D]
    const float* s = (const float*)d_in[3];      // [O]
    float* out = (float*)d_out;                  // [N, O]

    prep<<<2048 + OO, 256>>>(x, p, a, s);
    build_c<<<OO, 128>>>(p, a);
    cudaFuncSetAttribute(mobius_main, cudaFuncAttributeMaxDynamicSharedMemorySize,
                         SMEM_BYTES);
    dim3 grid(OO / BN, NN / BM);
    mobius_main<<<grid, 256, SMEM_BYTES>>>(out);
}

// round 13
// speedup vs baseline: 1.4397x; 1.0531x over previous
#include <cuda_runtime.h>
#include <cuda_fp16.h>
#include <math.h>
#include <cstdint>

#define NN 16384
#define DD 512
#define OO 512
#define BM 128
#define BN 128
#define BK 64                   // k-tile in elements (fp16)
#define NKT (DD / BK)           // 8 k-tiles
#define LH 72                   // smem fp16 per row (144B) -> conflict-free ldmatrix
#define TXH (BM * LH)           // 9216 halfs, X tile
#define TCH (BN * LH)           // 9216 halfs, C tile
#define STAGE_H (TXH + TCH)     // 18432 halfs = 36864 B
#define SMEM_BYTES (3 * STAGE_H * 2)  // 110592 B, 3 stages -> 2 CTAs/SM
#define MINN 1e-15f

// Precomputed stats + fp16 operands (no allocations -> device globals).
__device__ float g_a0[NN];    // 1 + ||x||^2
__device__ float g_rr[NN];    // 2 / (1 - ||x||^2)
__device__ float g_paq[OO];   // <p,a> / (B * ||a||)   (B = 1-||p||^2 in fp64)
__device__ float g_e2[OO];    // ln(2) * exp(scale)
__device__ __half g_Xh[NN * DD];
__device__ __half g_Ch[OO * DD];   // c = a/||a|| + 2*paq*p

__device__ __forceinline__ float warp_sum(float v) {
#pragma unroll
    for (int s = 16; s > 0; s >>= 1) v += __shfl_xor_sync(0xffffffffu, v, s);
    return v;
}
__device__ __forceinline__ double warp_sum_d(double v) {
#pragma unroll
    for (int s = 16; s > 0; s >>= 1) v += __shfl_xor_sync(0xffffffffu, v, s);
    return v;
}
__device__ __forceinline__ uint2 cvt4(float4 v) {
    __half2 h0 = __floats2half2_rn(v.x, v.y);
    __half2 h1 = __floats2half2_rn(v.z, v.w);
    uint2 u;
    u.x = *reinterpret_cast<uint32_t*>(&h0);
    u.y = *reinterpret_cast<uint32_t*>(&h1);
    return u;
}

// ---------------- fused prep ----------------
// blocks [0, 1024): X convert + x-stats, 2 rows per warp, MLP 8.
// blocks [1024, 1536): one block per o: stats (B in fp64) + build c, one pass.
__global__ void prep(const float* __restrict__ X, const float* __restrict__ P,
                     const float* __restrict__ A, const float* __restrict__ S) {
    int bid = blockIdx.x;
    int tid = threadIdx.x;
    int wid = tid >> 5, lane = tid & 31;
    if (bid < 1024) {
        int r0 = bid * 16 + wid * 2;
        const float4* x40 = reinterpret_cast<const float4*>(X + (size_t)r0 * DD);
        const float4* x41 = reinterpret_cast<const float4*>(X + (size_t)(r0 + 1) * DD);
        uint2* xh0 = reinterpret_cast<uint2*>(g_Xh + (size_t)r0 * DD);
        uint2* xh1 = reinterpret_cast<uint2*>(g_Xh + (size_t)(r0 + 1) * DD);
        float4 v0[4], v1[4];
#pragma unroll
        for (int j = 0; j < 4; j++) v0[j] = x40[lane + 32 * j];
#pragma unroll
        for (int j = 0; j < 4; j++) v1[j] = x41[lane + 32 * j];
        float s0 = 0.f, s1 = 0.f;
#pragma unroll
        for (int j = 0; j < 4; j++) {
            xh0[lane + 32 * j] = cvt4(v0[j]);
            xh1[lane + 32 * j] = cvt4(v1[j]);
            s0 += v0[j].x * v0[j].x + v0[j].y * v0[j].y +
                  v0[j].z * v0[j].z + v0[j].w * v0[j].w;
            s1 += v1[j].x * v1[j].x + v1[j].y * v1[j].y +
                  v1[j].z * v1[j].z + v1[j].w * v1[j].w;
        }
        s0 = warp_sum(s0);
        s1 = warp_sum(s1);
        if (lane == 0) {
            g_a0[r0] = 1.f + s0;
            g_rr[r0] = 2.f / (1.f - s0);
            g_a0[r0 + 1] = 1.f + s1;
            g_rr[r0 + 1] = 2.f / (1.f - s1);
        }
    } else {
        int o = bid - 1024;
        __shared__ double sp2[4];
        __shared__ float spa[4], sa2[4];
        __shared__ float sh_paq2, sh_ran;
        float4 pv, av;
        if (tid < 128) {
            const float4* p4 = reinterpret_cast<const float4*>(P + (size_t)o * DD);
            const float4* a4 = reinterpret_cast<const float4*>(A + (size_t)o * DD);
            pv = p4[tid];
            av = a4[tid];
            double p2 = (double)pv.x * pv.x + (double)pv.y * pv.y +
                        (double)pv.z * pv.z + (double)pv.w * pv.w;
            float pa = pv.x * av.x + pv.y * av.y + pv.z * av.z + pv.w * av.w;
            float a2 = av.x * av.x + av.y * av.y + av.z * av.z + av.w * av.w;
            p2 = warp_sum_d(p2);
            pa = warp_sum(pa);
            a2 = warp_sum(a2);
            if (lane == 0) { sp2[wid] = p2; spa[wid] = pa; sa2[wid] = a2; }
        }
        __syncthreads();
        if (tid == 0) {
            double tp2 = sp2[0] + sp2[1] + sp2[2] + sp2[3];
            double tpa = (double)spa[0] + spa[1] + spa[2] + spa[3];
            double ta2 = (double)sa2[0] + sa2[1] + sa2[2] + sa2[3];
            double B = 1.0 - tp2;    // catastrophic cancellation handled in fp64
            double an = sqrt(ta2);
            if (an < (double)MINN) an = (double)MINN;
            double paq = tpa / (B * an);
            g_paq[o] = (float)paq;
            g_e2[o] = 0.69314718055994530942f * expf(S[o]);
            sh_paq2 = (float)(2.0 * paq);
            sh_ran = (float)(1.0 / an);
        }
        __syncthreads();
        if (tid < 128) {
            float paq2 = sh_paq2, ran = sh_ran;
            uint2* ch = reinterpret_cast<uint2*>(g_Ch + (size_t)o * DD);
            float4 c;
            c.x = fmaf(paq2, pv.x, av.x * ran);
            c.y = fmaf(paq2, pv.y, av.y * ran);
            c.z = fmaf(paq2, pv.z, av.z * ran);
            c.w = fmaf(paq2, pv.w, av.w * ran);
            ch[tid] = cvt4(c);
        }
    }
}

// ---------------- PTX helpers ----------------
#define MMA_F16(d, a, b0, b1)                                                  \
    asm volatile(                                                              \
        "mma.sync.aligned.m16n8k16.row.col.f32.f16.f16.f32 "                   \
        "{%0,%1,%2,%3}, {%4,%5,%6,%7}, {%8,%9}, {%0,%1,%2,%3};"                \
        : "+f"((d)[0]), "+f"((d)[1]), "+f"((d)[2]), "+f"((d)[3])               \
        : "r"((a)[0]), "r"((a)[1]), "r"((a)[2]), "r"((a)[3]), "r"(b0), "r"(b1))

#define LDMX4(r, addr)                                                         \
    asm volatile("ldmatrix.sync.aligned.m8n8.x4.shared.b16 {%0,%1,%2,%3}, [%4];" \
                 : "=r"((r)[0]), "=r"((r)[1]), "=r"((r)[2]), "=r"((r)[3])      \
                 : "r"(addr))

#define CPA16(saddr, gptr)                                                     \
    asm volatile("cp.async.cg.shared.global [%0], [%1], 16;"                   \
                 :: "r"(saddr), "l"(gptr))
#define CPA_COMMIT() asm volatile("cp.async.commit_group;" ::: "memory")
#define CPA_WAIT1() asm volatile("cp.async.wait_group 1;" ::: "memory")

// asinh(arg)*e^s: asinh t = ln(t+sqrt(t^2+1)) = lg2(.)*ln2.
// Fast path (warp-uniform): all lanes |t| >= 64 -> asinh(t) ~= ln(2t).
__device__ __forceinline__ float epi(float xc, float a0, float rr,
                                     float paq, float e2) {
    float arg = (xc - a0 * paq) * rr;
    float tt = fabsf(arg);
    float u;
    if (__any_sync(0xffffffffu, tt < 64.f)) {
        float s;
        asm("sqrt.approx.f32 %0, %1;" : "=f"(s) : "f"(fmaf(tt, tt, 1.f)));
        u = tt + s;
    } else {
        u = tt + tt;
    }
    float r;
    asm("lg2.approx.f32 %0, %1;" : "=f"(r) : "f"(u));
    return copysignf(r * e2, arg);
}

// ---------------- main: SINGLE fp16 GEMM (x @ c^T) + tiny epilogue -----------
// 128x128 block tile, 256 threads, warp grid 2(M) x 4(N), warp tile 64x32.
__global__ void __launch_bounds__(256, 2) mobius_main(float* __restrict__ out) {
    extern __shared__ __half smh[];
    int tid = threadIdx.x;
    int lane = tid & 31, wid = tid >> 5;
    int wm = wid & 1, wn = wid >> 1;
    int m0 = blockIdx.y * BM, n0 = blockIdx.x * BN;

    const __half* Xg = g_Xh + (size_t)m0 * DD;
    const __half* Cg = g_Ch + (size_t)n0 * DD;
    uint32_t sbase = (uint32_t)__cvta_generic_to_shared(smh);

#define LOAD_STAGE(stg, kt)                                                    \
    {                                                                          \
        uint32_t st = sbase + (uint32_t)(stg) * (STAGE_H * 2);                 \
        int k0 = (kt) * BK;                                                    \
        _Pragma("unroll") for (int j = 0; j < 4; j++) {  /* 1024 chunks ea */  \
            int f = tid + 256 * j;                                             \
            int row = f >> 3, ck = f & 7;                                      \
            uint32_t so = (uint32_t)(row * (LH * 2) + ck * 16);                \
            size_t go = (size_t)row * DD + k0 + ck * 8;                        \
            CPA16(st + so, Xg + go);                                           \
            CPA16(st + TXH * 2 + so, Cg + go);                                 \
        }                                                                      \
    }

    float acc[4][4][4];
#pragma unroll
    for (int mt = 0; mt < 4; mt++)
#pragma unroll
        for (int nt = 0; nt < 4; nt++)
#pragma unroll
            for (int e = 0; e < 4; e++) acc[mt][nt][e] = 0.f;

    LOAD_STAGE(0, 0); CPA_COMMIT();
    LOAD_STAGE(1, 1); CPA_COMMIT();

    // ldmatrix per-lane base addresses (bytes, within a stage)
    uint32_t a_base = (uint32_t)(((wm * 64 + (lane & 15)) * LH + ((lane >> 4) << 3)) * 2);
    uint32_t b_row = (uint32_t)(wn * 32 + (((lane >> 4) & 1) << 3) + (lane & 7));
    uint32_t b_base = (uint32_t)((b_row * LH + (((lane >> 3) & 1) << 3)) * 2);

    for (int c = 0; c < NKT; ++c) {
        CPA_WAIT1();
        __syncthreads();
        if (c + 2 < NKT) { LOAD_STAGE((c + 2) % 3, c + 2); }
        CPA_COMMIT();

        uint32_t st = sbase + (uint32_t)(c % 3) * (STAGE_H * 2);
        uint32_t aA = st + a_base;
        uint32_t aC = st + TXH * 2 + b_base;
#pragma unroll
        for (int ks = 0; ks < 4; ks++) {    // 4 x k16 per k-tile of 64
            uint32_t af[4][4], bc[2][4];
#pragma unroll
            for (int mt = 0; mt < 4; mt++)
                LDMX4(af[mt], aA + (uint32_t)(mt * 16 * LH * 2 + ks * 32));
            LDMX4(bc[0], aC + (uint32_t)(ks * 32));
            LDMX4(bc[1], aC + (uint32_t)(16 * LH * 2 + ks * 32));
#pragma unroll
            for (int nt = 0; nt < 4; nt++) {
                uint32_t b0 = bc[nt >> 1][2 * (nt & 1)];
                uint32_t b1 = bc[nt >> 1][2 * (nt & 1) + 1];
#pragma unroll
                for (int mt = 0; mt < 4; mt++)
                    MMA_F16(acc[mt][nt], af[mt], b0, b1);
            }
        }
    }

    // ---- epilogue: arg = (xc - a0*paq)*rr; dist = asinh(arg)*e^s ----
    int g = lane >> 2, t = lane & 3;
    float a0r[4][2], rrr[4][2];
#pragma unroll
    for (int mt = 0; mt < 4; mt++)
#pragma unroll
        for (int h = 0; h < 2; h++) {
            int r = m0 + wm * 64 + mt * 16 + g + h * 8;
            a0r[mt][h] = g_a0[r];
            rrr[mt][h] = g_rr[r];
        }
    float paqc[4][2], e2c[4][2];
#pragma unroll
    for (int nt = 0; nt < 4; nt++)
#pragma unroll
        for (int w = 0; w < 2; w++) {
            int cc = n0 + wn * 32 + nt * 8 + 2 * t + w;
            paqc[nt][w] = g_paq[cc];
            e2c[nt][w] = g_e2[cc];
        }
#pragma unroll
    for (int mt = 0; mt < 4; mt++) {
#pragma unroll
        for (int h = 0; h < 2; h++) {
            int r = m0 + wm * 64 + mt * 16 + g + h * 8;
            float* orow = out + (size_t)r * OO + n0 + wn * 32 + 2 * t;
#pragma unroll
            for (int nt = 0; nt < 4; nt++) {
                float o0 = epi(acc[mt][nt][h * 2 + 0], a0r[mt][h], rrr[mt][h],
                               paqc[nt][0], e2c[nt][0]);
                float o1 = epi(acc[mt][nt][h * 2 + 1], a0r[mt][h], rrr[mt][h],
                               paqc[nt][1], e2c[nt][1]);
                *reinterpret_cast<float2*>(orow + nt * 8) = make_float2(o0, o1);
            }
        }
    }
}

extern "C" void kernel_launch(void* const* d_in, const int* in_sizes, int n_in,
                              void* d_out, int out_size) {
    const float* x = (const float*)d_in[0];      // [N, D]
    const float* p = (const float*)d_in[1];      // [O, D]
    const float* a = (const float*)d_in[2];      // [O, D]
    const float* s = (const float*)d_in[3];      // [O]
    float* out = (float*)d_out;                  // [N, O]

    prep<<<1024 + OO, 256>>>(x, p, a, s);
    cudaFuncSetAttribute(mobius_main, cudaFuncAttributeMaxDynamicSharedMemorySize,
                         SMEM_BYTES);
    dim3 grid(OO / BN, NN / BM);
    mobius_main<<<grid, 256, SMEM_BYTES>>>(out);
}